// round 2
// baseline (speedup 1.0000x reference)
#include <cuda_runtime.h>
#include <cstdint>

// Problem constants (from reference)
#define B_      2
#define N_IN    163842
#define N_OUT   40962
#define C_      128
#define K_      7
#define INV_2SIG2 3.125f   // 1/(2*0.4^2)

#define DOWN_ELEMS (B_ * N_OUT * C_)   // 10,486,272 floats (~42 MB)

// Scratch (allocation-free rule: __device__ globals)
__device__ float g_down[DOWN_ELEMS];
__device__ float g_denom[N_OUT];

// ---------------------------------------------------------------------------
// Kernel 0: zero scratch
// ---------------------------------------------------------------------------
__global__ void zero_kernel() {
    int i = blockIdx.x * blockDim.x + threadIdx.x;
    int stride = gridDim.x * blockDim.x;
    float4 z = make_float4(0.f, 0.f, 0.f, 0.f);
    float4* d4 = reinterpret_cast<float4*>(g_down);
    const int n4 = DOWN_ELEMS / 4;
    for (int t = i; t < n4; t += stride) d4[t] = z;
    for (int t = i; t < N_OUT; t += stride) g_denom[t] = 0.f;
}

// ---------------------------------------------------------------------------
// Kernel 1: scatter-add  down[b, parent[n], :] += omega[n] * x[b, n, :]
//           denom[parent[n]] += omega[n]
// One warp per n; lane handles 4 channels (float4), both batches.
// ---------------------------------------------------------------------------
__device__ __forceinline__ void red_add_v4(float* addr, float4 v) {
    asm volatile("red.global.add.v4.f32 [%0], {%1, %2, %3, %4};"
                 :: "l"(addr), "f"(v.x), "f"(v.y), "f"(v.z), "f"(v.w)
                 : "memory");
}

__global__ void __launch_bounds__(256)
scatter_kernel(const float* __restrict__ x,
               const float* __restrict__ omega,
               const int*   __restrict__ parent)
{
    int w    = (blockIdx.x * blockDim.x + threadIdx.x) >> 5;
    int lane = threadIdx.x & 31;
    if (w >= N_IN) return;
    const int n = w;

    const int   p  = __ldg(parent + n);   // uniform within warp -> broadcast
    const float om = __ldg(omega + n);

    const float4 v0i = reinterpret_cast<const float4*>(x + (size_t)n * C_)[lane];
    const float4 v1i = reinterpret_cast<const float4*>(x + (size_t)(N_IN + n) * C_)[lane];

    float4 v0 = make_float4(v0i.x * om, v0i.y * om, v0i.z * om, v0i.w * om);
    float4 v1 = make_float4(v1i.x * om, v1i.y * om, v1i.z * om, v1i.w * om);

    float* d0 = g_down + (size_t)p * C_ + lane * 4;
    float* d1 = g_down + (size_t)(N_OUT + p) * C_ + lane * 4;
    red_add_v4(d0, v0);
    red_add_v4(d1, v1);

    if (lane == 0) atomicAdd(g_denom + p, om);
}

// ---------------------------------------------------------------------------
// Kernel 2: gather  out[b,n,:] = sum_k coef_k * down_sum[b, cand[n,k], :]
//   coef_k = w_k / ( clip(sum_k w_k) * clip(denom[cand[n,k]]) )
//   w_k = exp(-delta^2 * INV_2SIG2) * mask
// One warp per n; lanes 0..6 compute per-k quantities, shfl-broadcast.
// This folds the down/denom normalization pass into the gather coefficient,
// saving a full 84 MB read+write normalize pass over g_down.
// ---------------------------------------------------------------------------
__global__ void __launch_bounds__(256)
gather_kernel(const float* __restrict__ delta,
              const float* __restrict__ mask,
              const int*   __restrict__ cand,
              float*       __restrict__ out)
{
    int w    = (blockIdx.x * blockDim.x + threadIdx.x) >> 5;
    int lane = threadIdx.x & 31;
    if (w >= N_IN) return;
    const int n = w;

    int   j  = 0;
    float e  = 0.f;
    float dn = 1.f;
    if (lane < K_) {
        const int idx = n * K_ + lane;
        j = __ldg(cand + idx);
        const float d = __ldg(delta + idx);
        e = __expf(-d * d * INV_2SIG2) * __ldg(mask + idx);
        dn = fmaxf(__ldg(g_denom + j), 1e-8f);
    }

    // sum of w over lanes 0..6 (lane 7 contributes 0); lanes 0..7 closed
    // under xor {1,2,4}
    float s = e;
    s += __shfl_xor_sync(0xffffffffu, s, 1);
    s += __shfl_xor_sync(0xffffffffu, s, 2);
    s += __shfl_xor_sync(0xffffffffu, s, 4);
    s  = __shfl_sync(0xffffffffu, s, 0);

    const float coef = e / (fmaxf(s, 1e-8f) * dn);  // lanes >= K_: e=0 -> 0

    float4 acc0 = make_float4(0.f, 0.f, 0.f, 0.f);
    float4 acc1 = make_float4(0.f, 0.f, 0.f, 0.f);

#pragma unroll
    for (int k = 0; k < K_; k++) {
        const int   jk = __shfl_sync(0xffffffffu, j,    k);
        const float ck = __shfl_sync(0xffffffffu, coef, k);
        const float4 v0 = reinterpret_cast<const float4*>(g_down + (size_t)jk * C_)[lane];
        const float4 v1 = reinterpret_cast<const float4*>(g_down + (size_t)(N_OUT + jk) * C_)[lane];
        acc0.x += ck * v0.x; acc0.y += ck * v0.y;
        acc0.z += ck * v0.z; acc0.w += ck * v0.w;
        acc1.x += ck * v1.x; acc1.y += ck * v1.y;
        acc1.z += ck * v1.z; acc1.w += ck * v1.w;
    }

    reinterpret_cast<float4*>(out + (size_t)n * C_)[lane]            = acc0;
    reinterpret_cast<float4*>(out + (size_t)(N_IN + n) * C_)[lane]   = acc1;
}

// ---------------------------------------------------------------------------
// Launch
// Inputs (metadata order): 0=x, 1=omega, 2=delta, 3=cand_mask, 4=parent_idx,
//                          5=cand_idx. Output: float32 [B, N_IN, C].
// ---------------------------------------------------------------------------
extern "C" void kernel_launch(void* const* d_in, const int* in_sizes, int n_in,
                              void* d_out, int out_size)
{
    const float* x      = (const float*)d_in[0];
    const float* omega  = (const float*)d_in[1];
    const float* delta  = (const float*)d_in[2];
    const float* mask   = (const float*)d_in[3];
    const int*   parent = (const int*)  d_in[4];
    const int*   cand   = (const int*)  d_in[5];
    float*       out    = (float*)d_out;

    zero_kernel<<<2048, 256>>>();

    const int warps  = N_IN;                 // one warp per n
    const int blocks = (warps * 32 + 255) / 256;
    scatter_kernel<<<blocks, 256>>>(x, omega, parent);
    gather_kernel<<<blocks, 256>>>(delta, mask, cand, out);
}

// round 4
// speedup vs baseline: 1.0756x; 1.0756x over previous
#include <cuda_runtime.h>
#include <cuda_fp16.h>
#include <cstdint>

// Problem constants (from reference)
#define B_      2
#define N_IN    163842
#define N_OUT   40962
#define C_      128
#define K_      7
#define INV_2SIG2 3.125f   // 1/(2*0.4^2)

#define DOWN_ELEMS (B_ * N_OUT * C_)   // 10,486,272 floats (~42 MB)

// Scratch (allocation-free rule: __device__ globals).
// CUDA zero-initializes device globals at module load; the convert pass
// re-zeroes g_down/g_denom after consuming them, so the "zero at entry"
// invariant holds on every call with no separate zero kernel.
__device__ float  g_down[DOWN_ELEMS];
__device__ float  g_denom[N_OUT];
// fp16 normalized intermediate, batch-interleaved: row j = [b0 c0..127][b1 c0..127]
// = 256 halves = 512 contiguous bytes per candidate row.
__device__ __half g_half[(size_t)N_OUT * 256];

// Bit-cast helpers (no SASS cost)
__device__ __forceinline__ unsigned h2_to_u(__half2 h) {
    unsigned u; *reinterpret_cast<__half2*>(&u) = h; return u;
}
__device__ __forceinline__ __half2 u_to_h2(unsigned u) {
    return *reinterpret_cast<__half2*>(&u);
}

// ---------------------------------------------------------------------------
// Kernel 1: scatter-add  down[b, parent[n], :] += omega[n] * x[b, n, :]
//           denom[parent[n]] += omega[n]
// One warp per n; lane handles 4 channels (float4), both batches.
// ---------------------------------------------------------------------------
__device__ __forceinline__ void red_add_v4(float* addr, float4 v) {
    asm volatile("red.global.add.v4.f32 [%0], {%1, %2, %3, %4};"
                 :: "l"(addr), "f"(v.x), "f"(v.y), "f"(v.z), "f"(v.w)
                 : "memory");
}

__global__ void __launch_bounds__(256)
scatter_kernel(const float* __restrict__ x,
               const float* __restrict__ omega,
               const int*   __restrict__ parent)
{
    int w    = (blockIdx.x * blockDim.x + threadIdx.x) >> 5;
    int lane = threadIdx.x & 31;
    if (w >= N_IN) return;
    const int n = w;

    const int   p  = __ldg(parent + n);   // uniform within warp -> broadcast
    const float om = __ldg(omega + n);

    const float4 v0i = reinterpret_cast<const float4*>(x + (size_t)n * C_)[lane];
    const float4 v1i = reinterpret_cast<const float4*>(x + (size_t)(N_IN + n) * C_)[lane];

    float4 v0 = make_float4(v0i.x * om, v0i.y * om, v0i.z * om, v0i.w * om);
    float4 v1 = make_float4(v1i.x * om, v1i.y * om, v1i.z * om, v1i.w * om);

    float* d0 = g_down + (size_t)p * C_ + lane * 4;
    float* d1 = g_down + (size_t)(N_OUT + p) * C_ + lane * 4;
    red_add_v4(d0, v0);
    red_add_v4(d1, v1);

    if (lane == 0) atomicAdd(g_denom + p, om);
}

// ---------------------------------------------------------------------------
// Kernel 2: convert  g_half[j] = fp16( g_down[:, j, :] / clip(denom[j]) )
// Then re-zero g_down rows and denom[j] for the next call (same thread reads
// before writing zero -> trivially ordered; restores the entry invariant).
// One warp per j; lane handles 4 channels of each batch.
// ---------------------------------------------------------------------------
__global__ void __launch_bounds__(256)
convert_kernel()
{
    int w    = (blockIdx.x * blockDim.x + threadIdx.x) >> 5;
    int lane = threadIdx.x & 31;
    if (w >= N_OUT) return;
    const int j = w;

    const float inv = 1.f / fmaxf(g_denom[j], 1e-8f);

    float4* p0 = reinterpret_cast<float4*>(g_down + (size_t)j * C_) + lane;
    float4* p1 = reinterpret_cast<float4*>(g_down + (size_t)(N_OUT + j) * C_) + lane;
    const float4 v0 = *p0;
    const float4 v1 = *p1;

    __half2 h00 = __floats2half2_rn(v0.x * inv, v0.y * inv);
    __half2 h01 = __floats2half2_rn(v0.z * inv, v0.w * inv);
    __half2 h10 = __floats2half2_rn(v1.x * inv, v1.y * inv);
    __half2 h11 = __floats2half2_rn(v1.z * inv, v1.w * inv);

    uint2* row = reinterpret_cast<uint2*>(g_half + (size_t)j * 256);
    row[lane]      = make_uint2(h2_to_u(h00), h2_to_u(h01));
    row[32 + lane] = make_uint2(h2_to_u(h10), h2_to_u(h11));

    // restore zero invariant for the next call
    const float4 z = make_float4(0.f, 0.f, 0.f, 0.f);
    *p0 = z;
    *p1 = z;
    if (lane == 0) g_denom[j] = 0.f;
}

// ---------------------------------------------------------------------------
// Kernel 3: gather  out[b,n,:] = sum_k coef_k * g_half[cand[n,k], b, :]
//   coef_k = w_k / clip(sum_k w_k);  w_k = exp(-delta^2 * INV_2SIG2) * mask
// (denom normalization already folded into g_half by convert_kernel)
// One warp per n; lanes 0..6 compute per-k weights, shfl-broadcast.
// Each (n,k) touches one contiguous 512B fp16 row (both batches).
// ---------------------------------------------------------------------------
__global__ void __launch_bounds__(256)
gather_kernel(const float* __restrict__ delta,
              const float* __restrict__ mask,
              const int*   __restrict__ cand,
              float*       __restrict__ out)
{
    int w    = (blockIdx.x * blockDim.x + threadIdx.x) >> 5;
    int lane = threadIdx.x & 31;
    if (w >= N_IN) return;
    const int n = w;

    int   j = 0;
    float e = 0.f;
    if (lane < K_) {
        const int idx = n * K_ + lane;
        j = __ldg(cand + idx);
        const float d = __ldg(delta + idx);
        e = __expf(-d * d * INV_2SIG2) * __ldg(mask + idx);
    }

    // sum of w over lanes 0..6 (lane 7 contributes 0); lanes 0..7 closed
    // under xor {1,2,4}
    float s = e;
    s += __shfl_xor_sync(0xffffffffu, s, 1);
    s += __shfl_xor_sync(0xffffffffu, s, 2);
    s += __shfl_xor_sync(0xffffffffu, s, 4);
    s  = __shfl_sync(0xffffffffu, s, 0);

    const float coef = e / fmaxf(s, 1e-8f);  // lanes >= K_: e=0 -> 0

    float4 acc0 = make_float4(0.f, 0.f, 0.f, 0.f);
    float4 acc1 = make_float4(0.f, 0.f, 0.f, 0.f);

#pragma unroll
    for (int k = 0; k < K_; k++) {
        const int   jk = __shfl_sync(0xffffffffu, j,    k);
        const float ck = __shfl_sync(0xffffffffu, coef, k);
        const uint2* row = reinterpret_cast<const uint2*>(g_half + (size_t)jk * 256);
        const uint2 h0 = __ldg(row + lane);        // b0: channels lane*4..+3
        const uint2 h1 = __ldg(row + 32 + lane);   // b1

        const float2 f00 = __half22float2(u_to_h2(h0.x));
        const float2 f01 = __half22float2(u_to_h2(h0.y));
        const float2 f10 = __half22float2(u_to_h2(h1.x));
        const float2 f11 = __half22float2(u_to_h2(h1.y));

        acc0.x = fmaf(ck, f00.x, acc0.x); acc0.y = fmaf(ck, f00.y, acc0.y);
        acc0.z = fmaf(ck, f01.x, acc0.z); acc0.w = fmaf(ck, f01.y, acc0.w);
        acc1.x = fmaf(ck, f10.x, acc1.x); acc1.y = fmaf(ck, f10.y, acc1.y);
        acc1.z = fmaf(ck, f11.x, acc1.z); acc1.w = fmaf(ck, f11.y, acc1.w);
    }

    reinterpret_cast<float4*>(out + (size_t)n * C_)[lane]          = acc0;
    reinterpret_cast<float4*>(out + (size_t)(N_IN + n) * C_)[lane] = acc1;
}

// ---------------------------------------------------------------------------
// Launch
// Inputs (metadata order): 0=x, 1=omega, 2=delta, 3=cand_mask, 4=parent_idx,
//                          5=cand_idx. Output: float32 [B, N_IN, C].
// ---------------------------------------------------------------------------
extern "C" void kernel_launch(void* const* d_in, const int* in_sizes, int n_in,
                              void* d_out, int out_size)
{
    const float* x      = (const float*)d_in[0];
    const float* omega  = (const float*)d_in[1];
    const float* delta  = (const float*)d_in[2];
    const float* mask   = (const float*)d_in[3];
    const int*   parent = (const int*)  d_in[4];
    const int*   cand   = (const int*)  d_in[5];
    float*       out    = (float*)d_out;

    const int blocks_in  = (N_IN  * 32 + 255) / 256;  // one warp per n
    const int blocks_out = (N_OUT * 32 + 255) / 256;  // one warp per j

    scatter_kernel<<<blocks_in, 256>>>(x, omega, parent);
    convert_kernel<<<blocks_out, 256>>>();
    gather_kernel<<<blocks_in, 256>>>(delta, mask, cand, out);
}